// round 3
// baseline (speedup 1.0000x reference)
#include <cuda_runtime.h>
#include <math.h>

// Shapes
#define T_ 16
#define B_ 32
#define S_ 256
#define H_ 256
#define E_ 300
#define V_ 1000

// d_out packing (reference return order, flattened floats)
#define PROB_OFF 0
#define HT_OFF   512000
#define CT_OFF   520192
#define CTX_OFF  528384

// Scratch (device globals; no cudaMalloc allowed)
__device__ float g_xproj[512 * 1024];   // [t*32+b][4H]
__device__ float g_enct[8192 * 256];    // [s*32+b][H]
__device__ float g_dect[512 * 256];     // [t*32+b][H]
__device__ float g_outh[16 * 32 * 256]; // [t][b][h]
__device__ float g_comb[512 * 512];     // [t*32+b][2H]
__device__ float g_logits[512 * 1000];  // [t*32+b][V]
__device__ unsigned g_bar_count;        // monotonic grid barrier (replay-safe)

__device__ __forceinline__ float tanh_fast(float x) {
    float y;
    asm("tanh.approx.f32 %0, %1;" : "=f"(y) : "f"(x));
    return y;
}
__device__ __forceinline__ float sigmoidf_(float x) {
    return 1.f / (1.f + __expf(-x));
}

// ---------------------------------------------------------------------------
// Generic GEMM: C[M][N] = A[M][K] @ B[N][K]^T + bias[N]
// Optional Aidx: A row m is A[Aidx[m]] (embedding gather).
// 64x64 tile, TK=16, 256 threads, 4x4 register microtile, double-buffer regs.
// Requires: M % 64 == 0, K % 4 == 0, row byte stride % 16 == 0.
// ---------------------------------------------------------------------------
__global__ void gemm_bias_kernel(const float* __restrict__ A,
                                 const int* __restrict__ Aidx,
                                 const float* __restrict__ Bw,
                                 const float* __restrict__ bias,
                                 float* __restrict__ C,
                                 int M, int N, int K)
{
    __shared__ __align__(16) float As[16][64];
    __shared__ __align__(16) float Bs[16][64];

    int tid = threadIdx.x;
    int tx = tid & 15, ty = tid >> 4;
    int nbase = blockIdx.x * 64, mbase = blockIdx.y * 64;

    int lm  = tid >> 2;        // 0..63
    int lk4 = (tid & 3) << 2;  // 0,4,8,12

    const float* Arow;
    {
        int m = mbase + lm;
        long ar = Aidx ? (long)Aidx[m] : (long)m;
        Arow = A + ar * (long)K;
    }
    int bn = nbase + lm;
    const float* Brow = Bw + (long)bn * K;

    float acc[4][4];
#pragma unroll
    for (int i = 0; i < 4; i++)
#pragma unroll
        for (int j = 0; j < 4; j++) acc[i][j] = 0.f;

    int ktiles = (K + 15) >> 4;

    float4 av = make_float4(0.f, 0.f, 0.f, 0.f);
    float4 bv = make_float4(0.f, 0.f, 0.f, 0.f);
    if (lk4 < K)           av = *(const float4*)(Arow + lk4);
    if (bn < N && lk4 < K) bv = *(const float4*)(Brow + lk4);

    for (int kt = 0; kt < ktiles; ++kt) {
        __syncthreads();
        As[lk4 + 0][lm] = av.x; As[lk4 + 1][lm] = av.y;
        As[lk4 + 2][lm] = av.z; As[lk4 + 3][lm] = av.w;
        Bs[lk4 + 0][lm] = bv.x; Bs[lk4 + 1][lm] = bv.y;
        Bs[lk4 + 2][lm] = bv.z; Bs[lk4 + 3][lm] = bv.w;
        __syncthreads();

        int kb = (kt + 1) << 4;
        av = make_float4(0.f, 0.f, 0.f, 0.f);
        bv = make_float4(0.f, 0.f, 0.f, 0.f);
        if (kt + 1 < ktiles) {
            if (kb + lk4 < K)           av = *(const float4*)(Arow + kb + lk4);
            if (bn < N && kb + lk4 < K) bv = *(const float4*)(Brow + kb + lk4);
        }

#pragma unroll
        for (int k = 0; k < 16; ++k) {
            float4 a = *(const float4*)&As[k][ty << 2];
            float4 b = *(const float4*)&Bs[k][tx << 2];
            acc[0][0] += a.x * b.x; acc[0][1] += a.x * b.y; acc[0][2] += a.x * b.z; acc[0][3] += a.x * b.w;
            acc[1][0] += a.y * b.x; acc[1][1] += a.y * b.y; acc[1][2] += a.y * b.z; acc[1][3] += a.y * b.w;
            acc[2][0] += a.z * b.x; acc[2][1] += a.z * b.y; acc[2][2] += a.z * b.z; acc[2][3] += a.z * b.w;
            acc[3][0] += a.w * b.x; acc[3][1] += a.w * b.y; acc[3][2] += a.w * b.z; acc[3][3] += a.w * b.w;
        }
    }

#pragma unroll
    for (int i = 0; i < 4; i++) {
        int m = mbase + (ty << 2) + i;
#pragma unroll
        for (int j = 0; j < 4; j++) {
            int n = nbase + (tx << 2) + j;
            if (n < N) C[(long)m * N + n] = acc[i][j] + bias[n];
        }
    }
}

// ---------------------------------------------------------------------------
// Persistent LSTM: 128 CTAs x 128 threads, grid barrier between steps.
// CTA bk owns hidden units {2bk, 2bk+1}; warp w computes gate w (i,f,g,o)
// for both units across all 32 batches (lane = batch).
// ---------------------------------------------------------------------------
__global__ void __launch_bounds__(128, 1)
lstm_kernel(const float* __restrict__ xproj, const float* __restrict__ W_hh,
            const float* __restrict__ b_hh, const float* __restrict__ h0,
            const float* __restrict__ c0, float* __restrict__ outh,
            float* __restrict__ dhT, float* __restrict__ dcT)
{
    __shared__ __align__(16) float W_s[8][256]; // [gate*2+ul][k]
    __shared__ float h_s[32][257];              // padded: conflict-free
    __shared__ float g_sm[8][32];
    __shared__ float c_s[2][32];

    int tid = threadIdx.x, bk = blockIdx.x;
    int u0 = bk * 2;

    for (int i = tid; i < 2048; i += 128) {
        int lr = i >> 8, k = i & 255;
        int grow = (lr >> 1) * 256 + u0 + (lr & 1);
        W_s[lr][k] = W_hh[grow * 256 + k];
    }
    if (tid < 64) {
        int ul = tid >> 5, b = tid & 31;
        c_s[ul][b] = c0[b * 256 + u0 + ul];
    }

    int w = tid >> 5, lane = tid & 31;
    int lr0 = w * 2, lr1 = lr0 + 1;
    int rowg0 = w * 256 + u0, rowg1 = rowg0 + 1;
    float bh0 = b_hh[rowg0], bh1 = b_hh[rowg1];
    __syncthreads();

    for (int t = 0; t < 16; ++t) {
        const float* hsrc = (t == 0) ? h0 : (outh + (t - 1) * 8192);
        for (int i = tid; i < 8192; i += 128)
            h_s[i >> 8][i & 255] = __ldcg(hsrc + i);
        __syncthreads();

        float acc0 = 0.f, acc1 = 0.f;
#pragma unroll 8
        for (int k = 0; k < 256; k += 4) {
            float4 wA = *(const float4*)&W_s[lr0][k];
            float4 wB = *(const float4*)&W_s[lr1][k];
            float hv0 = h_s[lane][k + 0];
            float hv1 = h_s[lane][k + 1];
            float hv2 = h_s[lane][k + 2];
            float hv3 = h_s[lane][k + 3];
            acc0 += wA.x * hv0 + wA.y * hv1 + wA.z * hv2 + wA.w * hv3;
            acc1 += wB.x * hv0 + wB.y * hv1 + wB.z * hv2 + wB.w * hv3;
        }
        float xp0 = xproj[(t * 32 + lane) * 1024 + rowg0];
        float xp1 = xproj[(t * 32 + lane) * 1024 + rowg1];
        g_sm[lr0][lane] = acc0 + xp0 + bh0;
        g_sm[lr1][lane] = acc1 + xp1 + bh1;
        __syncthreads();

        if (tid < 64) {
            int ul = tid >> 5, b = tid & 31;
            float gi = g_sm[0 + ul][b];
            float gf = g_sm[2 + ul][b];
            float gg = g_sm[4 + ul][b];
            float go = g_sm[6 + ul][b];
            float c = sigmoidf_(gf) * c_s[ul][b] + sigmoidf_(gi) * tanhf(gg);
            float h = sigmoidf_(go) * tanhf(c);
            c_s[ul][b] = c;
            outh[t * 8192 + b * 256 + u0 + ul] = h;
            if (t == 15) {
                dhT[b * 256 + u0 + ul] = h;
                dcT[b * 256 + u0 + ul] = c;
            }
        }

        __threadfence();
        __syncthreads();
        if (tid == 0) {
            unsigned old = atomicAdd(&g_bar_count, 1u);
            unsigned target = old - (old & 127u) + 128u;
            while (*((volatile unsigned*)&g_bar_count) < target) __nanosleep(32);
        }
        __syncthreads();
    }
}

// ---------------------------------------------------------------------------
// Fused attention: scores (tanh) + mask + softmax over S + context.
// Grid (b=32, tgroup=4); block = one batch, 4 time steps, 256 threads.
// ---------------------------------------------------------------------------
__global__ void attn_kernel(const float* __restrict__ enct,
                            const float* __restrict__ enc,
                            const float* __restrict__ dect,
                            const float* __restrict__ wa,
                            const float* __restrict__ ba,
                            const int* __restrict__ lens,
                            float* __restrict__ dctx)
{
    __shared__ float dec_s[4][256];
    __shared__ float wa_s[256];
    __shared__ float sc_s[4][256];
    __shared__ float red_s[8];

    int b = blockIdx.x, t0 = blockIdx.y * 4, tid = threadIdx.x;
    int w = tid >> 5, lane = tid & 31;

    for (int i = tid; i < 1024; i += 256) {
        int j = i >> 8, k = i & 255;
        dec_s[j][k] = dect[((t0 + j) * 32 + b) * 256 + k];
    }
    wa_s[tid] = wa[tid];
    float bav = ba[0];
    int L = lens[b];
    __syncthreads();

    // scores: one warp per s, lanes split h
    for (int s = w; s < 256; s += 8) {
        const float* ebase = enct + (long)(s * 32 + b) * 256;
        float p0 = 0.f, p1 = 0.f, p2 = 0.f, p3 = 0.f;
#pragma unroll
        for (int j = 0; j < 8; j++) {
            int h = lane + 32 * j;
            float ev = ebase[h];
            float wv = wa_s[h];
            p0 += wv * tanh_fast(ev + dec_s[0][h]);
            p1 += wv * tanh_fast(ev + dec_s[1][h]);
            p2 += wv * tanh_fast(ev + dec_s[2][h]);
            p3 += wv * tanh_fast(ev + dec_s[3][h]);
        }
#pragma unroll
        for (int off = 16; off > 0; off >>= 1) {
            p0 += __shfl_xor_sync(0xffffffffu, p0, off);
            p1 += __shfl_xor_sync(0xffffffffu, p1, off);
            p2 += __shfl_xor_sync(0xffffffffu, p2, off);
            p3 += __shfl_xor_sync(0xffffffffu, p3, off);
        }
        if (lane == 0) {
            sc_s[0][s] = p0 + bav;
            sc_s[1][s] = p1 + bav;
            sc_s[2][s] = p2 + bav;
            sc_s[3][s] = p3 + bav;
        }
    }
    __syncthreads();

    // masked softmax over s (tid = s) for each of 4 t-rows
    for (int j = 0; j < 4; ++j) {
        float x = (tid < L) ? sc_s[j][tid] : -1e30f;
        float m = x;
#pragma unroll
        for (int off = 16; off > 0; off >>= 1)
            m = fmaxf(m, __shfl_xor_sync(0xffffffffu, m, off));
        if (lane == 0) red_s[w] = m;
        __syncthreads();
        if (tid == 0) {
            float mm = red_s[0];
            for (int i = 1; i < 8; i++) mm = fmaxf(mm, red_s[i]);
            red_s[0] = mm;
        }
        __syncthreads();
        float mx = red_s[0];
        float e = (tid < L) ? __expf(x - mx) : 0.f;
        float sv = e;
#pragma unroll
        for (int off = 16; off > 0; off >>= 1)
            sv += __shfl_xor_sync(0xffffffffu, sv, off);
        __syncthreads();   // everyone has read red_s[0] before overwrite
        if (lane == 0) red_s[w] = sv;
        __syncthreads();
        if (tid == 0) {
            float ss = 0.f;
            for (int i = 0; i < 8; i++) ss += red_s[i];
            red_s[0] = ss;
        }
        __syncthreads();
        float inv = 1.f / red_s[0];
        sc_s[j][tid] = e * inv;
        __syncthreads();
    }

    // context: thread = h
    float c[4] = {0.f, 0.f, 0.f, 0.f};
    for (int s = 0; s < L; ++s) {
        float v = enc[(long)(s * 32 + b) * 256 + tid];
#pragma unroll
        for (int j = 0; j < 4; j++) c[j] += sc_s[j][s] * v;
    }
#pragma unroll
    for (int j = 0; j < 4; j++)
        dctx[((b * 16) + t0 + j) * 256 + tid] = c[j];
}

// combined[t*32+b][0:256]=context[b][t], [256:512]=output[t][b]
__global__ void combine_kernel(const float* __restrict__ dctx,
                               const float* __restrict__ outh,
                               float* __restrict__ comb)
{
    int idx = blockIdx.x * 256 + threadIdx.x;
    int m = idx >> 9, k = idx & 511;
    int t = m >> 5, b = m & 31;
    float v = (k < 256) ? dctx[(b * 16 + t) * 256 + k]
                        : outh[t * 8192 + b * 256 + (k - 256)];
    comb[idx] = v;
}

// softmax over V=1000 per row (512 rows)
__global__ void softmaxV_kernel(const float* __restrict__ logits,
                                float* __restrict__ prob)
{
    __shared__ float red_s[8];
    int m = blockIdx.x, tid = threadIdx.x, w = tid >> 5, lane = tid & 31;
    const float* row = logits + (long)m * 1000;

    float mx = -1e30f;
    for (int v = tid; v < 1000; v += 256) mx = fmaxf(mx, row[v]);
#pragma unroll
    for (int off = 16; off > 0; off >>= 1)
        mx = fmaxf(mx, __shfl_xor_sync(0xffffffffu, mx, off));
    if (lane == 0) red_s[w] = mx;
    __syncthreads();
    if (tid == 0) {
        float mm = red_s[0];
        for (int i = 1; i < 8; i++) mm = fmaxf(mm, red_s[i]);
        red_s[0] = mm;
    }
    __syncthreads();
    mx = red_s[0];

    float ebuf[4];
    float sum = 0.f;
    int cnt = 0;
    for (int v = tid; v < 1000; v += 256) {
        float e = __expf(row[v] - mx);
        ebuf[cnt++] = e;
        sum += e;
    }
#pragma unroll
    for (int off = 16; off > 0; off >>= 1)
        sum += __shfl_xor_sync(0xffffffffu, sum, off);
    __syncthreads();   // protect red_s[0]
    if (lane == 0) red_s[w] = sum;
    __syncthreads();
    if (tid == 0) {
        float ss = 0.f;
        for (int i = 0; i < 8; i++) ss += red_s[i];
        red_s[0] = ss;
    }
    __syncthreads();
    float inv = 1.f / red_s[0];
    cnt = 0;
    for (int v = tid; v < 1000; v += 256)
        prob[(long)m * 1000 + v] = ebuf[cnt++] * inv;
}

extern "C" void kernel_launch(void* const* d_in, const int* in_sizes, int n_in,
                              void* d_out, int out_size)
{
    const int*   target = (const int*)  d_in[0];
    const float* h0     = (const float*)d_in[1];
    const float* c0     = (const float*)d_in[2];
    const float* enc    = (const float*)d_in[3];
    const int*   lens   = (const int*)  d_in[4];
    const float* emb    = (const float*)d_in[5];
    const float* W_ih   = (const float*)d_in[6];
    const float* W_hh   = (const float*)d_in[7];
    const float* b_ih   = (const float*)d_in[8];
    const float* b_hh   = (const float*)d_in[9];
    const float* We     = (const float*)d_in[10];
    const float* be     = (const float*)d_in[11];
    const float* Wd     = (const float*)d_in[12];
    const float* bd     = (const float*)d_in[13];
    const float* wa     = (const float*)d_in[14];
    const float* ba     = (const float*)d_in[15];
    const float* W_out  = (const float*)d_in[16];
    const float* b_out  = (const float*)d_in[17];
    float* out = (float*)d_out;

    float* xproj  = nullptr; cudaGetSymbolAddress((void**)&xproj,  g_xproj);
    float* enct   = nullptr; cudaGetSymbolAddress((void**)&enct,   g_enct);
    float* dect   = nullptr; cudaGetSymbolAddress((void**)&dect,   g_dect);
    float* outh   = nullptr; cudaGetSymbolAddress((void**)&outh,   g_outh);
    float* comb   = nullptr; cudaGetSymbolAddress((void**)&comb,   g_comb);
    float* logits = nullptr; cudaGetSymbolAddress((void**)&logits, g_logits);

    // 1) x_proj = emb[target] @ W_ih^T + b_ih   [512 x 1024]
    gemm_bias_kernel<<<dim3(16, 8), 256>>>(emb, target, W_ih, b_ih, xproj,
                                           512, 1024, 300);
    // 2) enc_t = enc @ We^T + be   [8192 x 256]
    gemm_bias_kernel<<<dim3(4, 128), 256>>>(enc, nullptr, We, be, enct,
                                            8192, 256, 256);
    // 3) LSTM chain -> outh, hT, cT
    lstm_kernel<<<128, 128>>>(xproj, W_hh, b_hh, h0, c0, outh,
                              out + HT_OFF, out + CT_OFF);
    // 4) dec_t = outh @ Wd^T + bd   [512 x 256]
    gemm_bias_kernel<<<dim3(4, 8), 256>>>(outh, nullptr, Wd, bd, dect,
                                          512, 256, 256);
    // 5) attention + context -> out[CTX]
    attn_kernel<<<dim3(32, 4), 256>>>(enct, enc, dect, wa, ba, lens,
                                      out + CTX_OFF);
    // 6) combined [512 x 512]
    combine_kernel<<<1024, 256>>>(out + CTX_OFF, outh, comb);
    // 7) logits = comb @ W_out^T + b_out   [512 x 1000]
    gemm_bias_kernel<<<dim3(16, 8), 256>>>(comb, nullptr, W_out, b_out, logits,
                                           512, 1000, 512);
    // 8) softmax over V -> out[PROB]
    softmaxV_kernel<<<512, 256>>>(logits, out + PROB_OFF);
}

// round 5
// speedup vs baseline: 1.0255x; 1.0255x over previous
#include <cuda_runtime.h>
#include <math.h>

// Shapes
#define T_ 16
#define B_ 32
#define S_ 256
#define H_ 256
#define E_ 300
#define V_ 1000

// d_out packing (reference return order, flattened floats)
#define PROB_OFF 0
#define HT_OFF   512000
#define CT_OFF   520192
#define CTX_OFF  528384

// Scratch (device globals; no cudaMalloc allowed)
__device__ float g_xproj[512 * 1024];    // [t*32+b][4H]
__device__ float g_enct[8192 * 256];     // PERMUTED: [b*256+s][H]  (zero-init; masked tiles stay 0)
__device__ float g_outh[16 * 32 * 256];  // [t][b][h]
__device__ float g_comb[512 * 512];      // [t*32+b][2H]
__device__ float g_logits[512 * 1000];   // [t*32+b][V]
__device__ float g_WdT[256 * 256];       // Wd transposed: [k][h]
__device__ unsigned g_bar_count;         // monotonic grid barrier (replay-safe)

__device__ __forceinline__ float tanh_fast(float x) {
    float y;
    asm("tanh.approx.f32 %0, %1;" : "=f"(y) : "f"(x));
    return y;
}
__device__ __forceinline__ float sigmoidf_(float x) {
    return 1.f / (1.f + __expf(-x));
}

// ---------------------------------------------------------------------------
// GEMM: C[M][N] = Arow(m) . Bw[n] + bias[n]   (B stored [N][K], i.e. C=A@B^T)
// Tile 64(M) x 64(N), TK=8, 128 threads, 8x4 register microtile (FMA-bound).
// MODE 0: Arow(m)=A[m]
// MODE 1: Arow(m)=A[Aidx[m]]                  (embedding gather)
// MODE 2: m = b*256+s -> Arow = A[s*32+b]; tile skipped if s0 >= lens[b]
// Requires M % 64 == 0. N, K arbitrary (guarded).
// ---------------------------------------------------------------------------
template <int MODE>
__global__ void __launch_bounds__(128)
gemm64_kernel(const float* __restrict__ A, const int* __restrict__ Aidx,
              const int* __restrict__ lens,
              const float* __restrict__ Bw, const float* __restrict__ bias,
              float* __restrict__ C, int M, int N, int K)
{
    __shared__ __align__(16) float As[8][64];
    __shared__ __align__(16) float Bs[8][64];

    int tid = threadIdx.x;
    int nbase = blockIdx.x * 64, mbase = blockIdx.y * 64;

    if (MODE == 2) {
        int b = mbase >> 8;
        if ((mbase & 255) >= lens[b]) return;   // whole tile masked
    }

    int lr  = tid >> 1;        // 0..63  (row within tile for loads)
    int lkq = (tid & 1) * 4;   // 0 or 4

    long arow;
    {
        int m = mbase + lr;
        if (MODE == 1)      arow = Aidx[m];
        else if (MODE == 2) { int b = m >> 8, s = m & 255; arow = (long)s * 32 + b; }
        else                arow = m;
    }
    const float* Ap = A + arow * (long)K;
    int bn = nbase + lr;
    const float* Bp = Bw + (long)bn * K;
    bool bval = (bn < N);

    int tx = tid & 15, ty = tid >> 4;  // tx 0..15 (N), ty 0..7 (M)

    float acc[8][4];
#pragma unroll
    for (int i = 0; i < 8; i++)
#pragma unroll
        for (int j = 0; j < 4; j++) acc[i][j] = 0.f;

    int ktiles = (K + 7) >> 3;

    float4 av = make_float4(0.f, 0.f, 0.f, 0.f);
    float4 bv = make_float4(0.f, 0.f, 0.f, 0.f);
    {
        int k = lkq;
        if (k + 3 < K) av = *(const float4*)(Ap + k);
        else { if (k < K) av.x = Ap[k]; if (k+1 < K) av.y = Ap[k+1];
               if (k+2 < K) av.z = Ap[k+2]; if (k+3 < K) av.w = Ap[k+3]; }
        if (bval) {
            if (k + 3 < K) bv = *(const float4*)(Bp + k);
            else { if (k < K) bv.x = Bp[k]; if (k+1 < K) bv.y = Bp[k+1];
                   if (k+2 < K) bv.z = Bp[k+2]; if (k+3 < K) bv.w = Bp[k+3]; }
        }
    }

    for (int kt = 0; kt < ktiles; ++kt) {
        __syncthreads();
        As[lkq + 0][lr] = av.x; As[lkq + 1][lr] = av.y;
        As[lkq + 2][lr] = av.z; As[lkq + 3][lr] = av.w;
        Bs[lkq + 0][lr] = bv.x; Bs[lkq + 1][lr] = bv.y;
        Bs[lkq + 2][lr] = bv.z; Bs[lkq + 3][lr] = bv.w;
        __syncthreads();

        // prefetch next tile
        av = make_float4(0.f, 0.f, 0.f, 0.f);
        bv = make_float4(0.f, 0.f, 0.f, 0.f);
        if (kt + 1 < ktiles) {
            int k = ((kt + 1) << 3) + lkq;
            if (k + 3 < K) av = *(const float4*)(Ap + k);
            else { if (k < K) av.x = Ap[k]; if (k+1 < K) av.y = Ap[k+1];
                   if (k+2 < K) av.z = Ap[k+2]; if (k+3 < K) av.w = Ap[k+3]; }
            if (bval) {
                if (k + 3 < K) bv = *(const float4*)(Bp + k);
                else { if (k < K) bv.x = Bp[k]; if (k+1 < K) bv.y = Bp[k+1];
                       if (k+2 < K) bv.z = Bp[k+2]; if (k+3 < K) bv.w = Bp[k+3]; }
            }
        }

#pragma unroll
        for (int k = 0; k < 8; ++k) {
            float4 a0 = *(const float4*)&As[k][ty * 4];
            float4 a1 = *(const float4*)&As[k][32 + ty * 4];
            float4 b  = *(const float4*)&Bs[k][tx * 4];
            acc[0][0] += a0.x * b.x; acc[0][1] += a0.x * b.y; acc[0][2] += a0.x * b.z; acc[0][3] += a0.x * b.w;
            acc[1][0] += a0.y * b.x; acc[1][1] += a0.y * b.y; acc[1][2] += a0.y * b.z; acc[1][3] += a0.y * b.w;
            acc[2][0] += a0.z * b.x; acc[2][1] += a0.z * b.y; acc[2][2] += a0.z * b.z; acc[2][3] += a0.z * b.w;
            acc[3][0] += a0.w * b.x; acc[3][1] += a0.w * b.y; acc[3][2] += a0.w * b.z; acc[3][3] += a0.w * b.w;
            acc[4][0] += a1.x * b.x; acc[4][1] += a1.x * b.y; acc[4][2] += a1.x * b.z; acc[4][3] += a1.x * b.w;
            acc[5][0] += a1.y * b.x; acc[5][1] += a1.y * b.y; acc[5][2] += a1.y * b.z; acc[5][3] += a1.y * b.w;
            acc[6][0] += a1.z * b.x; acc[6][1] += a1.z * b.y; acc[6][2] += a1.z * b.z; acc[6][3] += a1.z * b.w;
            acc[7][0] += a1.w * b.x; acc[7][1] += a1.w * b.y; acc[7][2] += a1.w * b.z; acc[7][3] += a1.w * b.w;
        }
    }

#pragma unroll
    for (int i = 0; i < 8; i++) {
        int mm = mbase + ((i < 4) ? (ty * 4 + i) : (32 + ty * 4 + (i - 4)));
#pragma unroll
        for (int j = 0; j < 4; j++) {
            int n = nbase + tx * 4 + j;
            if (n < N) C[(long)mm * N + n] = acc[i][j] + bias[n];
        }
    }
}

// Naive transpose: WdT[k][h] = Wd[h][k]  (256x256, tiny)
__global__ void transpose256_kernel(const float* __restrict__ in,
                                    float* __restrict__ out)
{
    int idx = blockIdx.x * 256 + threadIdx.x;  // idx = k*256 + h
    int k = idx >> 8, h = idx & 255;
    out[idx] = in[h * 256 + k];
}

// ---------------------------------------------------------------------------
// Persistent LSTM: 64 CTAs x 256 threads, grid barrier between steps.
// CTA bk owns hidden units u0..u0+3 (u0=4*bk); 16 gate-rows r=g*4+ul.
// Warp w computes rows 2w, 2w+1 across all 32 batches (lane = batch).
// Dynamic smem: W[16][256] | h[32][257] | g[16][32] | c[4][32]
// ---------------------------------------------------------------------------
__global__ void __launch_bounds__(256, 1)
lstm_kernel(const float* __restrict__ xproj, const float* __restrict__ W_hh,
            const float* __restrict__ b_hh, const float* __restrict__ h0,
            const float* __restrict__ c0, float* __restrict__ outh,
            float* __restrict__ comb,
            float* __restrict__ dhT, float* __restrict__ dcT)
{
    extern __shared__ float lsm[];
    float* W_sm = lsm;                 // 16*256
    float* h_sm = lsm + 4096;          // 32*257 (padded, conflict-free)
    float* g_sm = h_sm + 32 * 257;     // 16*32
    float* c_sm = g_sm + 512;          // 4*32

    int tid = threadIdx.x, bk = blockIdx.x;
    int u0 = bk * 4;

    // Load this CTA's 16 W_hh rows once: r=g*4+ul -> global row g*256+u0+ul
    for (int i = tid; i < 4096; i += 256) {
        int r = i >> 8, k = i & 255;
        int g = r >> 2, ul = r & 3;
        W_sm[r * 256 + k] = W_hh[(g * 256 + u0 + ul) * 256 + k];
    }
    if (tid < 128) {
        int ul = tid >> 5, b = tid & 31;
        c_sm[ul * 32 + b] = c0[b * 256 + u0 + ul];
    }

    int w = tid >> 5, lane = tid & 31;
    int r0 = 2 * w, r1 = 2 * w + 1;
    int g0 = r0 >> 2, ul0 = r0 & 3;
    int g1 = r1 >> 2, ul1 = r1 & 3;
    int rowg0 = g0 * 256 + u0 + ul0;
    int rowg1 = g1 * 256 + u0 + ul1;
    float bh0 = b_hh[rowg0], bh1 = b_hh[rowg1];
    __syncthreads();

    for (int t = 0; t < 16; ++t) {
        const float* hsrc = (t == 0) ? h0 : (outh + (t - 1) * 8192);
        for (int i = tid; i < 8192; i += 256) {
            int b = i >> 8, k = i & 255;
            h_sm[b * 257 + k] = __ldcg(hsrc + i);
        }
        __syncthreads();

        float acc0 = 0.f, acc1 = 0.f;
        const float* W0 = W_sm + r0 * 256;
        const float* W1 = W_sm + r1 * 256;
        const float* hrow = h_sm + lane * 257;
#pragma unroll 8
        for (int k = 0; k < 256; k += 4) {
            float4 wA = *(const float4*)(W0 + k);
            float4 wB = *(const float4*)(W1 + k);
            float hv0 = hrow[k + 0];
            float hv1 = hrow[k + 1];
            float hv2 = hrow[k + 2];
            float hv3 = hrow[k + 3];
            acc0 += wA.x * hv0 + wA.y * hv1 + wA.z * hv2 + wA.w * hv3;
            acc1 += wB.x * hv0 + wB.y * hv1 + wB.z * hv2 + wB.w * hv3;
        }
        float xp0 = xproj[(t * 32 + lane) * 1024 + rowg0];
        float xp1 = xproj[(t * 32 + lane) * 1024 + rowg1];
        g_sm[r0 * 32 + lane] = acc0 + xp0 + bh0;
        g_sm[r1 * 32 + lane] = acc1 + xp1 + bh1;
        __syncthreads();

        if (tid < 128) {
            int ul = tid >> 5, b = tid & 31;
            float gi = g_sm[(0 * 4 + ul) * 32 + b];
            float gf = g_sm[(1 * 4 + ul) * 32 + b];
            float gg = g_sm[(2 * 4 + ul) * 32 + b];
            float go = g_sm[(3 * 4 + ul) * 32 + b];
            float c = sigmoidf_(gf) * c_sm[ul * 32 + b] + sigmoidf_(gi) * tanhf(gg);
            float h = sigmoidf_(go) * tanhf(c);
            c_sm[ul * 32 + b] = c;
            int hu = u0 + ul;
            outh[t * 8192 + b * 256 + hu] = h;
            comb[(t * 32 + b) * 512 + 256 + hu] = h;   // right half of combined
            if (t == 15) {
                dhT[b * 256 + hu] = h;
                dcT[b * 256 + hu] = c;
            }
        }

        // Grid barrier (monotonic counter: replay-safe)
        __threadfence();
        __syncthreads();
        if (tid == 0) {
            unsigned old = atomicAdd(&g_bar_count, 1u);
            unsigned target = old - (old & 63u) + 64u;
            while (*((volatile unsigned*)&g_bar_count) < target) { }
        }
        __syncthreads();
    }
}

// ---------------------------------------------------------------------------
// Fused: dec_t (from WdT) + scores (tanh, s<L only) + masked softmax + context.
// Grid (b=32, tgroup=4); block = one batch, 4 time steps, 256 threads.
// Writes context to out[CTX] and to comb left half.
// ---------------------------------------------------------------------------
__global__ void __launch_bounds__(256)
attn_kernel(const float* __restrict__ enct,   // [b*256+s][H] (masked tiles = 0, never read)
            const float* __restrict__ enc,    // [s*32+b][H]
            const float* __restrict__ outh,   // [t][b][h]
            const float* __restrict__ WdT,    // [k][h]
            const float* __restrict__ bd,
            const float* __restrict__ wa,
            const float* __restrict__ ba,
            const int* __restrict__ lens,
            float* __restrict__ dctx,         // out + CTX_OFF, [b][t][h]
            float* __restrict__ comb)         // [t*32+b][2H]
{
    __shared__ __align__(16) float outh_s[4][256];
    __shared__ __align__(16) float dec_s[4][256];
    __shared__ float wa_s[256];
    __shared__ float sc_s[4][256];
    __shared__ float red_s[8];

    int b = blockIdx.x, t0 = blockIdx.y * 4, tid = threadIdx.x;
    int w = tid >> 5, lane = tid & 31;

    // load outh rows for 4 t's (vectorized)
    for (int i = tid; i < 256; i += 256) { }  // (no-op, keep structure simple)
    {
        int j = tid >> 6, q = (tid & 63) * 4;  // 4 rows x 64 float4
        float4 v = *(const float4*)(outh + (t0 + j) * 8192 + b * 256 + q);
        *(float4*)&outh_s[j][q] = v;
    }
    wa_s[tid] = wa[tid];
    float bav = ba[0];
    int L = lens[b];
    __syncthreads();

    // dec_t: thread h = tid; WdT reads coalesced over h
    {
        float a0 = 0.f, a1 = 0.f, a2 = 0.f, a3 = 0.f;
#pragma unroll 4
        for (int k = 0; k < 256; k += 4) {
            float w0 = WdT[(k + 0) * 256 + tid];
            float w1 = WdT[(k + 1) * 256 + tid];
            float w2 = WdT[(k + 2) * 256 + tid];
            float w3 = WdT[(k + 3) * 256 + tid];
            float4 o0 = *(const float4*)&outh_s[0][k];
            float4 o1 = *(const float4*)&outh_s[1][k];
            float4 o2 = *(const float4*)&outh_s[2][k];
            float4 o3 = *(const float4*)&outh_s[3][k];
            a0 += w0 * o0.x + w1 * o0.y + w2 * o0.z + w3 * o0.w;
            a1 += w0 * o1.x + w1 * o1.y + w2 * o1.z + w3 * o1.w;
            a2 += w0 * o2.x + w1 * o2.y + w2 * o2.z + w3 * o2.w;
            a3 += w0 * o3.x + w1 * o3.y + w2 * o3.z + w3 * o3.w;
        }
        float bdv = bd[tid];
        dec_s[0][tid] = a0 + bdv;
        dec_s[1][tid] = a1 + bdv;
        dec_s[2][tid] = a2 + bdv;
        dec_s[3][tid] = a3 + bdv;
    }
    __syncthreads();

    // scores: one warp per s (only s < L), lanes split h
    for (int s = w; s < L; s += 8) {
        const float* ebase = enct + ((long)b * 256 + s) * 256;
        float p0 = 0.f, p1 = 0.f, p2 = 0.f, p3 = 0.f;
#pragma unroll
        for (int j = 0; j < 8; j++) {
            int h = lane + 32 * j;
            float ev = ebase[h];
            float wv = wa_s[h];
            p0 += wv * tanh_fast(ev + dec_s[0][h]);
            p1 += wv * tanh_fast(ev + dec_s[1][h]);
            p2 += wv * tanh_fast(ev + dec_s[2][h]);
            p3 += wv * tanh_fast(ev + dec_s[3][h]);
        }
#pragma unroll
        for (int off = 16; off > 0; off >>= 1) {
            p0 += __shfl_xor_sync(0xffffffffu, p0, off);
            p1 += __shfl_xor_sync(0xffffffffu, p1, off);
            p2 += __shfl_xor_sync(0xffffffffu, p2, off);
            p3 += __shfl_xor_sync(0xffffffffu, p3, off);
        }
        if (lane == 0) {
            sc_s[0][s] = p0 + bav;
            sc_s[1][s] = p1 + bav;
            sc_s[2][s] = p2 + bav;
            sc_s[3][s] = p3 + bav;
        }
    }
    __syncthreads();

    // masked softmax over s (tid = s) for each of 4 t-rows
    for (int j = 0; j < 4; ++j) {
        float x = (tid < L) ? sc_s[j][tid] : -1e30f;
        float m = x;
#pragma unroll
        for (int off = 16; off > 0; off >>= 1)
            m = fmaxf(m, __shfl_xor_sync(0xffffffffu, m, off));
        if (lane == 0) red_s[w] = m;
        __syncthreads();
        if (tid == 0) {
            float mm = red_s[0];
            for (int i = 1; i < 8; i++) mm = fmaxf(mm, red_s[i]);
            red_s[0] = mm;
        }
        __syncthreads();
        float mx = red_s[0];
        float e = (tid < L) ? __expf(x - mx) : 0.f;
        float sv = e;
#pragma unroll
        for (int off = 16; off > 0; off >>= 1)
            sv += __shfl_xor_sync(0xffffffffu, sv, off);
        __syncthreads();
        if (lane == 0) red_s[w] = sv;
        __syncthreads();
        if (tid == 0) {
            float ss = 0.f;
            for (int i = 0; i < 8; i++) ss += red_s[i];
            red_s[0] = ss;
        }
        __syncthreads();
        float inv = 1.f / red_s[0];
        sc_s[j][tid] = e * inv;
        __syncthreads();
    }

    // context: thread = h
    float c[4] = {0.f, 0.f, 0.f, 0.f};
    for (int s = 0; s < L; ++s) {
        float v = enc[((long)s * 32 + b) * 256 + tid];
#pragma unroll
        for (int j = 0; j < 4; j++) c[j] += sc_s[j][s] * v;
    }
#pragma unroll
    for (int j = 0; j < 4; j++) {
        int t = t0 + j;
        dctx[(b * 16 + t) * 256 + tid] = c[j];
        comb[(t * 32 + b) * 512 + tid] = c[j];   // left half of combined
    }
}

// softmax over V=1000 per row (512 rows)
__global__ void softmaxV_kernel(const float* __restrict__ logits,
                                float* __restrict__ prob)
{
    __shared__ float red_s[8];
    int m = blockIdx.x, tid = threadIdx.x, w = tid >> 5, lane = tid & 31;
    const float* row = logits + (long)m * 1000;

    float mx = -1e30f;
    for (int v = tid; v < 1000; v += 256) mx = fmaxf(mx, row[v]);
#pragma unroll
    for (int off = 16; off > 0; off >>= 1)
        mx = fmaxf(mx, __shfl_xor_sync(0xffffffffu, mx, off));
    if (lane == 0) red_s[w] = mx;
    __syncthreads();
    if (tid == 0) {
        float mm = red_s[0];
        for (int i = 1; i < 8; i++) mm = fmaxf(mm, red_s[i]);
        red_s[0] = mm;
    }
    __syncthreads();
    mx = red_s[0];

    float ebuf[4];
    float sum = 0.f;
    int cnt = 0;
    for (int v = tid; v < 1000; v += 256) {
        float e = __expf(row[v] - mx);
        ebuf[cnt++] = e;
        sum += e;
    }
#pragma unroll
    for (int off = 16; off > 0; off >>= 1)
        sum += __shfl_xor_sync(0xffffffffu, sum, off);
    __syncthreads();
    if (lane == 0) red_s[w] = sum;
    __syncthreads();
    if (tid == 0) {
        float ss = 0.f;
        for (int i = 0; i < 8; i++) ss += red_s[i];
        red_s[0] = ss;
    }
    __syncthreads();
    float inv = 1.f / red_s[0];
    cnt = 0;
    for (int v = tid; v < 1000; v += 256)
        prob[(long)m * 1000 + v] = ebuf[cnt++] * inv;
}

extern "C" void kernel_launch(void* const* d_in, const int* in_sizes, int n_in,
                              void* d_out, int out_size)
{
    const int*   target = (const int*)  d_in[0];
    const float* h0     = (const float*)d_in[1];
    const float* c0     = (const float*)d_in[2];
    const float* enc    = (const float*)d_in[3];
    const int*   lens   = (const int*)  d_in[4];
    const float* emb    = (const float*)d_in[5];
    const float* W_ih   = (const float*)d_in[6];
    const float* W_hh   = (const float*)d_in[7];
    const float* b_ih   = (const float*)d_in[8];
    const float* b_hh   = (const float*)d_in[9];
    const float* We     = (const float*)d_in[10];
    const float* be     = (const float*)d_in[11];
    const float* Wd     = (const float*)d_in[12];
    const float* bd     = (const float*)d_in[13];
    const float* wa     = (const float*)d_in[14];
    const float* ba     = (const float*)d_in[15];
    const float* W_out  = (const float*)d_in[16];
    const float* b_out  = (const float*)d_in[17];
    float* out = (float*)d_out;

    float* xproj  = nullptr; cudaGetSymbolAddress((void**)&xproj,  g_xproj);
    float* enct   = nullptr; cudaGetSymbolAddress((void**)&enct,   g_enct);
    float* outh   = nullptr; cudaGetSymbolAddress((void**)&outh,   g_outh);
    float* comb   = nullptr; cudaGetSymbolAddress((void**)&comb,   g_comb);
    float* logits = nullptr; cudaGetSymbolAddress((void**)&logits, g_logits);
    float* WdT    = nullptr; cudaGetSymbolAddress((void**)&WdT,    g_WdT);

    static int smem_set = 0;
    if (!smem_set) {
        cudaFuncSetAttribute(lstm_kernel,
                             cudaFuncAttributeMaxDynamicSharedMemorySize, 52000);
        smem_set = 1;
    }

    // 0) WdT = Wd^T (tiny; needed by attn)
    transpose256_kernel<<<256, 256>>>(Wd, WdT);
    // 1) x_proj = emb[target] @ W_ih^T + b_ih   [512 x 1024], K=300
    gemm64_kernel<1><<<dim3(16, 8), 128>>>(emb, target, nullptr, W_ih, b_ih,
                                           xproj, 512, 1024, 300);
    // 2) enc_t (permuted [b][s][h]) = enc @ We^T + be, tiles with s>=len skipped
    gemm64_kernel<2><<<dim3(4, 128), 128>>>(enc, nullptr, lens, We, be,
                                            enct, 8192, 256, 256);
    // 3) LSTM chain -> outh, comb(right), hT, cT
    lstm_kernel<<<64, 256, 52000>>>(xproj, W_hh, b_hh, h0, c0, outh, comb,
                                    out + HT_OFF, out + CT_OFF);
    // 4) attention (dec_t fused) -> out[CTX], comb(left)
    attn_kernel<<<dim3(32, 4), 256>>>(enct, enc, outh, WdT, bd, wa, ba, lens,
                                      out + CTX_OFF, comb);
    // 5) logits = comb @ W_out^T + b_out   [512 x 1000], K=512
    gemm64_kernel<0><<<dim3(16, 8), 128>>>(comb, nullptr, nullptr, W_out, b_out,
                                           logits, 512, 1000, 512);
    // 6) softmax over V -> out[PROB]
    softmaxV_kernel<<<512, 256>>>(logits, out + PROB_OFF);
}